// round 8
// baseline (speedup 1.0000x reference)
#include <cuda_runtime.h>
#include <cuda_bf16.h>
#include <cstdint>

#define NN 100000
#define NE 1200000
#define HH 64
#define H2 128
#define NB_SCAN 98

// ---------------- device scratch (no allocations allowed) ----------------
__device__ float g_z[NN * HH];      // layer input features (fp32)
__device__ float g_h[NN * HH];      // residual stream (fp32)
__device__ unsigned g_uh[NN * 32];  // MLP input, bf16x2 hi words (k-pairs)
__device__ unsigned g_ul[NN * 32];  // MLP input, bf16x2 lo words
__device__ int   g_rowptr[NN + 1];
__device__ int   g_wp[NN];          // zeroed by previous replay's k_final
__device__ int   g_srcs[NE];        // src ids PRE-SCALED by 64
__device__ int   g_sval[128];
__device__ int   g_sincl[128];
__device__ int   g_sflag[128];      // tail-zeroed by k_final
// pre-split weights, [n][kp] rows (k contiguous as bf16):
__device__ unsigned g_w1h[3 * 4096], g_w1l[3 * 4096];
__device__ unsigned g_w2h[3 * 4096], g_w2l[3 * 4096];

// ---------------- helpers ----------------
__device__ __forceinline__ float ex2(float x) {
    float r; asm("ex2.approx.f32 %0, %1;" : "=f"(r) : "f"(x)); return r;
}
__device__ __forceinline__ unsigned pk_bf2(float xe, float xo) {
    unsigned d;
    asm("cvt.rn.bf16x2.f32 %0, %1, %2;" : "=r"(d) : "f"(xo), "f"(xe));
    return d;
}
__device__ __forceinline__ float lo16f(unsigned w) { return __uint_as_float(w << 16); }
__device__ __forceinline__ float hi16f(unsigned w) { return __uint_as_float(w & 0xffff0000u); }
__device__ __forceinline__ void split_pair(float xe, float xo, unsigned& hw, unsigned& lw) {
    hw = pk_bf2(xe, xo);
    lw = pk_bf2(xe - lo16f(hw), xo - hi16f(hw));
}
__device__ __forceinline__ uint32_t smem_u32(const void* p) {
    uint32_t a;
    asm("{ .reg .u64 t; cvta.to.shared.u64 t, %1; cvt.u32.u64 %0, t; }" : "=r"(a) : "l"(p));
    return a;
}
__device__ __forceinline__ void mma16(float* c, unsigned a0, unsigned a1,
                                      unsigned a2, unsigned a3,
                                      unsigned b0, unsigned b1) {
    asm("mma.sync.aligned.m16n8k16.row.col.f32.bf16.bf16.f32 "
        "{%0,%1,%2,%3}, {%4,%5,%6,%7}, {%8,%9}, {%0,%1,%2,%3};"
        : "+f"(c[0]), "+f"(c[1]), "+f"(c[2]), "+f"(c[3])
        : "r"(a0), "r"(a1), "r"(a2), "r"(a3), "r"(b0), "r"(b1));
}
__device__ __forceinline__ void ldsm4(unsigned& r0, unsigned& r1, unsigned& r2,
                                      unsigned& r3, uint32_t addr) {
    asm volatile("ldmatrix.sync.aligned.m8n8.x4.shared.b16 {%0,%1,%2,%3}, [%4];"
                 : "=r"(r0), "=r"(r1), "=r"(r2), "=r"(r3) : "r"(addr));
}

// ------ launch 0: encoder + degree histogram + weight pre-split ------
__global__ void k_enc_hist(const float* __restrict__ x, const float* __restrict__ W,
                           const float* __restrict__ b, const int* __restrict__ ei,
                           const float* __restrict__ W1g, const float* __restrict__ W2g) {
    int idx = blockIdx.x * blockDim.x + threadIdx.x;
    if (idx == 0) g_rowptr[NN] = NE;
    if (idx < NE) atomicAdd(&g_wp[ei[NE + idx]], 1);
    if (idx < NN * HH) {
        int n = idx >> 6, c = idx & 63;
        g_z[idx] = x[n * 3] * W[c] + x[n * 3 + 1] * W[HH + c]
                 + x[n * 3 + 2] * W[2 * HH + c] + b[c];
    }
    if (idx < 3 * 4096) {   // W1^T: idx = l*4096 + n*32 + kp
        int l = idx >> 12, r = idx & 4095, n = r >> 5, kp = r & 31;
        const float* Wl = W1g + l * (HH * H2);
        unsigned hw, lw;
        split_pair(Wl[(2 * kp) * H2 + n], Wl[(2 * kp + 1) * H2 + n], hw, lw);
        g_w1h[idx] = hw; g_w1l[idx] = lw;
    }
    if (idx < 3 * 4096) {   // W2^T: idx = l*4096 + n*64 + kp
        int l = idx >> 12, r = idx & 4095, n = r >> 6, kp = r & 63;
        const float* Wl = W2g + l * (H2 * HH);
        unsigned hw, lw;
        split_pair(Wl[(2 * kp) * HH + n], Wl[(2 * kp + 1) * HH + n], hw, lw);
        g_w2h[idx] = hw; g_w2l[idx] = lw;
    }
}

// ------------- launch 1: single-pass scan (decoupled lookback) -------------
__global__ void k_scan() {
    __shared__ int wsum[32];
    __shared__ int s_excl;
    int t = threadIdx.x, b = blockIdx.x;
    int lane = t & 31, wid = t >> 5;
    int i = b * 1024 + t;
    int x = (i < NN) ? g_wp[i] : 0;

    int v = x;
#pragma unroll
    for (int d = 1; d < 32; d <<= 1) {
        int u = __shfl_up_sync(0xffffffffu, v, d);
        if (lane >= d) v += u;
    }
    if (lane == 31) wsum[wid] = v;
    __syncthreads();
    if (wid == 0) {
        int w = wsum[lane];
#pragma unroll
        for (int d = 1; d < 32; d <<= 1) {
            int u = __shfl_up_sync(0xffffffffu, w, d);
            if (lane >= d) w += u;
        }
        wsum[lane] = w;
    }
    __syncthreads();
    int incl = v + (wid ? wsum[wid - 1] : 0);
    int bsum = wsum[31];

    if (t == 0) {
        if (b == 0) {
            g_sincl[0] = bsum; __threadfence(); g_sflag[0] = 2;
            s_excl = 0;
        } else {
            g_sval[b] = bsum; __threadfence(); g_sflag[b] = 1;
            int excl = 0, j = b - 1;
            while (true) {
                int f;
                do { f = ((volatile int*)g_sflag)[j]; } while (f == 0);
                __threadfence();
                if (f == 2) { excl += ((volatile int*)g_sincl)[j]; break; }
                excl += ((volatile int*)g_sval)[j]; j--;
            }
            g_sincl[b] = excl + bsum; __threadfence(); g_sflag[b] = 2;
            s_excl = excl;
        }
    }
    __syncthreads();
    if (i < NN) {
        int e = s_excl + incl - x;
        g_rowptr[i] = e;
        g_wp[i] = e;
    }
}

// ------------- launch 2: scatter src ids (pre-scaled) into CSR -------------
__global__ void k_scatter(const int* __restrict__ ei) {
    int e = blockIdx.x * blockDim.x + threadIdx.x;
    if (e < NE) {
        int d = ei[NE + e];
        int p = atomicAdd(&g_wp[d], 1);
        g_srcs[p] = ei[e] << 6;   // src * HH
    }
}

// ------- single-pass softmax aggregation, 4-deep pipelined gathers --------
__global__ void k_agg(const float* __restrict__ tptr) {
    int gw = (blockIdx.x * blockDim.x + threadIdx.x) >> 5;
    if (gw >= NN) return;
    int lane = threadIdx.x & 31;
    int beg = g_rowptr[gw], end = g_rowptr[gw + 1];
    float tl2 = __ldg(tptr) * 1.44269504f;
    const float* zp = g_z + 2 * lane;

    float za0 = 0.f, za1 = 0.f, sa0 = 0.f, sa1 = 0.f;
    float zb0 = 0.f, zb1 = 0.f, sb0 = 0.f, sb1 = 0.f;
    float zc0 = 0.f, zc1 = 0.f, sc0 = 0.f, sc1 = 0.f;
    float zd0 = 0.f, zd1 = 0.f, sd0 = 0.f, sd1 = 0.f;

    for (int base = beg; base < end; base += 32) {
        int nn = end - base; if (nn > 32) nn = 32;
        int sid = (base + lane < end) ? __ldg(&g_srcs[base + lane]) : 0;
        int j = 0;
        for (; j + 4 <= nn; j += 4) {
            int s0 = __shfl_sync(0xffffffffu, sid, j);
            int s1 = __shfl_sync(0xffffffffu, sid, j + 1);
            int s2 = __shfl_sync(0xffffffffu, sid, j + 2);
            int s3 = __shfl_sync(0xffffffffu, sid, j + 3);
            float2 v0 = *(const float2*)(zp + s0);
            float2 v1 = *(const float2*)(zp + s1);
            float2 v2 = *(const float2*)(zp + s2);
            float2 v3 = *(const float2*)(zp + s3);
            float r, w;
            r = fmaxf(v0.x, 0.f); w = ex2(r * tl2); za0 += w; sa0 = fmaf(r, w, sa0);
            r = fmaxf(v0.y, 0.f); w = ex2(r * tl2); za1 += w; sa1 = fmaf(r, w, sa1);
            r = fmaxf(v1.x, 0.f); w = ex2(r * tl2); zb0 += w; sb0 = fmaf(r, w, sb0);
            r = fmaxf(v1.y, 0.f); w = ex2(r * tl2); zb1 += w; sb1 = fmaf(r, w, sb1);
            r = fmaxf(v2.x, 0.f); w = ex2(r * tl2); zc0 += w; sc0 = fmaf(r, w, sc0);
            r = fmaxf(v2.y, 0.f); w = ex2(r * tl2); zc1 += w; sc1 = fmaf(r, w, sc1);
            r = fmaxf(v3.x, 0.f); w = ex2(r * tl2); zd0 += w; sd0 = fmaf(r, w, sd0);
            r = fmaxf(v3.y, 0.f); w = ex2(r * tl2); zd1 += w; sd1 = fmaf(r, w, sd1);
        }
        for (; j < nn; j++) {
            int s0 = __shfl_sync(0xffffffffu, sid, j);
            float2 v0 = *(const float2*)(zp + s0);
            float r, w;
            r = fmaxf(v0.x, 0.f); w = ex2(r * tl2); za0 += w; sa0 = fmaf(r, w, sa0);
            r = fmaxf(v0.y, 0.f); w = ex2(r * tl2); za1 += w; sa1 = fmaf(r, w, sa1);
        }
    }
    float z0 = (za0 + zb0) + (zc0 + zd0);
    float z1 = (za1 + zb1) + (zc1 + zd1);
    float s0 = (sa0 + sb0) + (sc0 + sd0);
    float s1 = (sa1 + sb1) + (sc1 + sd1);

    float2 zz = *(const float2*)(g_z + gw * HH + 2 * lane);
    float ox = zz.x, oy = zz.y;
    if (end > beg) {
        ox += __fdividef(s0, z0) + 1e-7f;
        oy += __fdividef(s1, z1) + 1e-7f;
    }
    unsigned hw, lw;
    split_pair(ox, oy, hw, lw);
    g_uh[gw * 32 + lane] = hw;
    g_ul[gw * 32 + lane] = lw;
}

// -------- fused MLP: bf16 mma.sync + ldmatrix, 3-term emulated fp32 -------
// also (wz=1) fuses the NEXT layer's z = relu(LN(h)) epilogue.
#define W_PSUM 0
#define W_PSQ  128
#define W_B1   256
#define W_GAM  384
#define W_BET  512
#define W_B2   640
#define W_A    704
#define W_UH   (W_A)
#define W_UL   (W_A + 2304)
#define W_HH   (W_A)
#define W_HL   (W_A + 4352)
#define W_W1H  9408
#define W_W1L  14016
#define W_W2H  18624
#define W_W2L  22976
#define SMEM_MLP_BYTES (27328 * 4)

extern __shared__ unsigned smw[];
__global__ __launch_bounds__(256, 2) void k_mlp(
    const float* __restrict__ b1g, const float* __restrict__ gamg,
    const float* __restrict__ betg, const float* __restrict__ b2g,
    const float* __restrict__ lngN, const float* __restrict__ lnbN,
    int layer, int addm, int wz)
{
    float* smf = (float*)smw;
    int tid = threadIdx.x, w = tid >> 5, lane = tid & 31;
    int g = lane >> 2, t4 = lane & 3;
    int wm = w & 3, wn = w >> 2;
    int n0 = blockIdx.x * 64;
    int lofs = layer * 4096;

    if (tid < 128) {
        smf[W_B1 + tid]  = b1g[tid];
        smf[W_GAM + tid] = gamg[tid];
        smf[W_BET + tid] = betg[tid];
        if (tid < 64) smf[W_B2 + tid] = b2g[tid];
    }
    for (int i = tid * 4; i < 2048; i += 1024) {
        int r = i >> 5, c = i & 31;
        int node = n0 + r;
        uint4 hv = make_uint4(0, 0, 0, 0), lv = hv;
        if (node < NN) {
            hv = *(const uint4*)&g_uh[node * 32 + c];
            lv = *(const uint4*)&g_ul[node * 32 + c];
        }
        *(uint4*)&smw[W_UH + r * 36 + c] = hv;
        *(uint4*)&smw[W_UL + r * 36 + c] = lv;
    }
    for (int i = tid * 4; i < 4096; i += 1024) {
        int r = i >> 5, c = i & 31;
        *(uint4*)&smw[W_W1H + r * 36 + c] = *(const uint4*)&g_w1h[lofs + i];
        *(uint4*)&smw[W_W1L + r * 36 + c] = *(const uint4*)&g_w1l[lofs + i];
    }
    for (int i = tid * 4; i < 4096; i += 1024) {
        int r = i >> 6, c = i & 63;
        *(uint4*)&smw[W_W2H + r * 68 + c] = *(const uint4*)&g_w2h[lofs + i];
        *(uint4*)&smw[W_W2L + r * 68 + c] = *(const uint4*)&g_w2l[lofs + i];
    }
    __syncthreads();

    uint32_t sb = smem_u32(smw);
    int lr = (lane & 7) + ((lane >> 3) & 1) * 8;
    int lhalf = lane >> 4;
    int l8 = lane & 7, lg = lane >> 3;

    // ---- GEMM1 ----
    uint32_t a1H = sb + W_UH * 4 + (16 * wm + lr) * 144 + lhalf * 16;
    uint32_t a1L = a1H + (W_UL - W_UH) * 4;
    uint32_t b1H = sb + W_W1H * 4 + (64 * wn + l8) * 144 + lg * 16;
    uint32_t b1L = b1H + (W_W1L - W_W1H) * 4;

    unsigned aH[4][4], aL[4][4];
#pragma unroll
    for (int ks = 0; ks < 4; ks++) {
        ldsm4(aH[ks][0], aH[ks][1], aH[ks][2], aH[ks][3], a1H + ks * 32);
        ldsm4(aL[ks][0], aL[ks][1], aL[ks][2], aL[ks][3], a1L + ks * 32);
    }
    float c1[8][4];
#pragma unroll
    for (int j = 0; j < 8; j++)
#pragma unroll
        for (int q = 0; q < 4; q++) c1[j][q] = 0.f;

#pragma unroll
    for (int j = 0; j < 8; j++) {
        uint32_t bj = b1H + j * 1152, bjL = b1L + j * 1152;
#pragma unroll
        for (int p = 0; p < 2; p++) {
            unsigned h0, h1, h2, h3, l0, l1, l2, l3;
            ldsm4(h0, h1, h2, h3, bj + p * 64);
            ldsm4(l0, l1, l2, l3, bjL + p * 64);
            int ka = 2 * p, kb = 2 * p + 1;
            mma16(c1[j], aH[ka][0], aH[ka][1], aH[ka][2], aH[ka][3], h0, h1);
            mma16(c1[j], aH[ka][0], aH[ka][1], aH[ka][2], aH[ka][3], l0, l1);
            mma16(c1[j], aL[ka][0], aL[ka][1], aL[ka][2], aL[ka][3], h0, h1);
            mma16(c1[j], aH[kb][0], aH[kb][1], aH[kb][2], aH[kb][3], h2, h3);
            mma16(c1[j], aH[kb][0], aH[kb][1], aH[kb][2], aH[kb][3], l2, l3);
            mma16(c1[j], aL[kb][0], aL[kb][1], aL[kb][2], aL[kb][3], h2, h3);
        }
    }

    // ---- epilogue 1: bias + LN(128) partial sums ----
    int r0 = 16 * wm + g, r1 = r0 + 8;
    float sA = 0.f, sqA = 0.f, sB = 0.f, sqB = 0.f;
#pragma unroll
    for (int j = 0; j < 8; j++) {
        int cb = 64 * wn + 8 * j + 2 * t4;
        float bx = smf[W_B1 + cb], by = smf[W_B1 + cb + 1];
        c1[j][0] += bx; c1[j][1] += by; c1[j][2] += bx; c1[j][3] += by;
        sA += c1[j][0] + c1[j][1];
        sqA = fmaf(c1[j][0], c1[j][0], fmaf(c1[j][1], c1[j][1], sqA));
        sB += c1[j][2] + c1[j][3];
        sqB = fmaf(c1[j][2], c1[j][2], fmaf(c1[j][3], c1[j][3], sqB));
    }
    sA += __shfl_xor_sync(0xffffffffu, sA, 1);  sA += __shfl_xor_sync(0xffffffffu, sA, 2);
    sqA += __shfl_xor_sync(0xffffffffu, sqA, 1); sqA += __shfl_xor_sync(0xffffffffu, sqA, 2);
    sB += __shfl_xor_sync(0xffffffffu, sB, 1);  sB += __shfl_xor_sync(0xffffffffu, sB, 2);
    sqB += __shfl_xor_sync(0xffffffffu, sqB, 1); sqB += __shfl_xor_sync(0xffffffffu, sqB, 2);
    if (t4 == 0) {
        smf[W_PSUM + wn * 64 + r0] = sA;  smf[W_PSQ + wn * 64 + r0] = sqA;
        smf[W_PSUM + wn * 64 + r1] = sB;  smf[W_PSQ + wn * 64 + r1] = sqB;
    }
    __syncthreads();

    float s0 = smf[W_PSUM + r0] + smf[W_PSUM + 64 + r0];
    float q0 = smf[W_PSQ + r0]  + smf[W_PSQ + 64 + r0];
    float s1 = smf[W_PSUM + r1] + smf[W_PSUM + 64 + r1];
    float q1 = smf[W_PSQ + r1]  + smf[W_PSQ + 64 + r1];
    float mu0 = s0 * (1.f / 128.f), mu1 = s1 * (1.f / 128.f);
    float rs0 = rsqrtf(q0 * (1.f / 128.f) - mu0 * mu0 + 1e-5f);
    float rs1 = rsqrtf(q1 * (1.f / 128.f) - mu1 * mu1 + 1e-5f);

#pragma unroll
    for (int j = 0; j < 8; j++) {
        int cb = 64 * wn + 8 * j + 2 * t4;
        float gx = smf[W_GAM + cb], gy = smf[W_GAM + cb + 1];
        float ex = smf[W_BET + cb], ey = smf[W_BET + cb + 1];
        float h0 = fmaxf((c1[j][0] - mu0) * rs0 * gx + ex, 0.f);
        float h1 = fmaxf((c1[j][1] - mu0) * rs0 * gy + ey, 0.f);
        float h2 = fmaxf((c1[j][2] - mu1) * rs1 * gx + ex, 0.f);
        float h3 = fmaxf((c1[j][3] - mu1) * rs1 * gy + ey, 0.f);
        int kp = cb >> 1;
        unsigned hw, lw;
        split_pair(h0, h1, hw, lw);
        smw[W_HH + r0 * 68 + kp] = hw; smw[W_HL + r0 * 68 + kp] = lw;
        split_pair(h2, h3, hw, lw);
        smw[W_HH + r1 * 68 + kp] = hw; smw[W_HL + r1 * 68 + kp] = lw;
    }
    __syncthreads();

    // ---- GEMM2 ----
    uint32_t a2H = sb + W_HH * 4 + (16 * wm + lr) * 272 + lhalf * 16;
    uint32_t a2L = a2H + (W_HL - W_HH) * 4;
    uint32_t b2H = sb + W_W2H * 4 + (32 * wn + l8) * 272 + lg * 16;
    uint32_t b2L = b2H + (W_W2L - W_W2H) * 4;

    float c2[4][4];
#pragma unroll
    for (int j = 0; j < 4; j++)
#pragma unroll
        for (int q = 0; q < 4; q++) c2[j][q] = 0.f;

#pragma unroll
    for (int p = 0; p < 4; p++) {
        unsigned xh[8], xl[8];
        ldsm4(xh[0], xh[1], xh[2], xh[3], a2H + p * 64);
        ldsm4(xh[4], xh[5], xh[6], xh[7], a2H + p * 64 + 32);
        ldsm4(xl[0], xl[1], xl[2], xl[3], a2L + p * 64);
        ldsm4(xl[4], xl[5], xl[6], xl[7], a2L + p * 64 + 32);
#pragma unroll
        for (int j = 0; j < 4; j++) {
            unsigned h0, h1, h2, h3, l0, l1, l2, l3;
            ldsm4(h0, h1, h2, h3, b2H + j * 2176 + p * 64);
            ldsm4(l0, l1, l2, l3, b2L + j * 2176 + p * 64);
            mma16(c2[j], xh[0], xh[1], xh[2], xh[3], h0, h1);
            mma16(c2[j], xh[0], xh[1], xh[2], xh[3], l0, l1);
            mma16(c2[j], xl[0], xl[1], xl[2], xl[3], h0, h1);
            mma16(c2[j], xh[4], xh[5], xh[6], xh[7], h2, h3);
            mma16(c2[j], xh[4], xh[5], xh[6], xh[7], l2, l3);
            mma16(c2[j], xl[4], xl[5], xl[6], xl[7], h2, h3);
        }
    }

    // ---- epilogue 2: bias (+residual) -> g_h ; keep final h in c2 ----
    int node0 = n0 + r0, node1 = n0 + r1;
    float ps0 = 0.f, pq0 = 0.f, ps1 = 0.f, pq1 = 0.f;
#pragma unroll
    for (int j = 0; j < 4; j++) {
        int cb = 32 * wn + 8 * j + 2 * t4;
        float bx = smf[W_B2 + cb], by = smf[W_B2 + cb + 1];
        float h00 = c2[j][0] + bx, h01 = c2[j][1] + by;
        float h10 = c2[j][2] + bx, h11 = c2[j][3] + by;
        if (node0 < NN) {
            float* dst = g_h + node0 * HH + cb;
            if (addm) { float2 pv = *(const float2*)dst; h00 += pv.x; h01 += pv.y; }
            *(float2*)dst = make_float2(h00, h01);
        }
        if (node1 < NN) {
            float* dst = g_h + node1 * HH + cb;
            if (addm) { float2 pv = *(const float2*)dst; h10 += pv.x; h11 += pv.y; }
            *(float2*)dst = make_float2(h10, h11);
        }
        c2[j][0] = h00; c2[j][1] = h01; c2[j][2] = h10; c2[j][3] = h11;
        ps0 += h00 + h01; pq0 = fmaf(h00, h00, fmaf(h01, h01, pq0));
        ps1 += h10 + h11; pq1 = fmaf(h10, h10, fmaf(h11, h11, pq1));
    }

    // ---- fused z = relu(LN_{next}(h)) (wz layers only) ----
    if (wz) {
        ps0 += __shfl_xor_sync(0xffffffffu, ps0, 1); ps0 += __shfl_xor_sync(0xffffffffu, ps0, 2);
        pq0 += __shfl_xor_sync(0xffffffffu, pq0, 1); pq0 += __shfl_xor_sync(0xffffffffu, pq0, 2);
        ps1 += __shfl_xor_sync(0xffffffffu, ps1, 1); ps1 += __shfl_xor_sync(0xffffffffu, ps1, 2);
        pq1 += __shfl_xor_sync(0xffffffffu, pq1, 1); pq1 += __shfl_xor_sync(0xffffffffu, pq1, 2);
        if (t4 == 0) {
            smf[W_PSUM + wn * 64 + r0] = ps0;  smf[W_PSQ + wn * 64 + r0] = pq0;
            smf[W_PSUM + wn * 64 + r1] = ps1;  smf[W_PSQ + wn * 64 + r1] = pq1;
        }
        __syncthreads();
        float S0 = smf[W_PSUM + r0] + smf[W_PSUM + 64 + r0];
        float Q0 = smf[W_PSQ + r0]  + smf[W_PSQ + 64 + r0];
        float S1 = smf[W_PSUM + r1] + smf[W_PSUM + 64 + r1];
        float Q1 = smf[W_PSQ + r1]  + smf[W_PSQ + 64 + r1];
        float m0 = S0 * (1.f / 64.f), m1 = S1 * (1.f / 64.f);
        float v0 = rsqrtf(Q0 * (1.f / 64.f) - m0 * m0 + 1e-5f);
        float v1 = rsqrtf(Q1 * (1.f / 64.f) - m1 * m1 + 1e-5f);
#pragma unroll
        for (int j = 0; j < 4; j++) {
            int cb = 32 * wn + 8 * j + 2 * t4;
            float gx = __ldg(&lngN[cb]), gy = __ldg(&lngN[cb + 1]);
            float ex = __ldg(&lnbN[cb]), ey = __ldg(&lnbN[cb + 1]);
            if (node0 < NN) {
                float z0 = fmaxf((c2[j][0] - m0) * v0 * gx + ex, 0.f);
                float z1 = fmaxf((c2[j][1] - m0) * v0 * gy + ey, 0.f);
                *(float2*)(g_z + node0 * HH + cb) = make_float2(z0, z1);
            }
            if (node1 < NN) {
                float z0 = fmaxf((c2[j][2] - m1) * v1 * gx + ex, 0.f);
                float z1 = fmaxf((c2[j][3] - m1) * v1 * gy + ey, 0.f);
                *(float2*)(g_z + node1 * HH + cb) = make_float2(z0, z1);
            }
        }
    }
}

// -------- final: relu(LN(h)) @ lin_W + lin_b ; also re-zero scratch --------
__global__ void k_final(const float* __restrict__ g, const float* __restrict__ b,
                        const float* __restrict__ lw, const float* __restrict__ lb,
                        float* __restrict__ out) {
    int gw = (blockIdx.x * blockDim.x + threadIdx.x) >> 5;
    if (gw >= NN) return;
    int lane = threadIdx.x & 31;
    if (lane == 1) g_wp[gw] = 0;
    if (gw < 128 && lane == 2) g_sflag[gw] = 0;

    float2 v = *(const float2*)(g_h + gw * HH + 2 * lane);
    float s = v.x + v.y, sq = v.x * v.x + v.y * v.y;
    for (int o = 16; o; o >>= 1) {
        s  += __shfl_xor_sync(0xffffffffu, s, o);
        sq += __shfl_xor_sync(0xffffffffu, sq, o);
    }
    float mu = s * 0.015625f;
    float var = sq * 0.015625f - mu * mu;
    float rs = rsqrtf(var + 1e-5f);
    float a0 = fmaxf((v.x - mu) * rs * g[2 * lane]     + b[2 * lane],     0.f);
    float a1 = fmaxf((v.y - mu) * rs * g[2 * lane + 1] + b[2 * lane + 1], 0.f);
    float o0 = a0 * lw[(2 * lane) * 3 + 0] + a1 * lw[(2 * lane + 1) * 3 + 0];
    float o1 = a0 * lw[(2 * lane) * 3 + 1] + a1 * lw[(2 * lane + 1) * 3 + 1];
    float o2 = a0 * lw[(2 * lane) * 3 + 2] + a1 * lw[(2 * lane + 1) * 3 + 2];
    for (int ww = 16; ww; ww >>= 1) {
        o0 += __shfl_xor_sync(0xffffffffu, o0, ww);
        o1 += __shfl_xor_sync(0xffffffffu, o1, ww);
        o2 += __shfl_xor_sync(0xffffffffu, o2, ww);
    }
    if (lane == 0) {
        out[gw * 3 + 0] = o0 + lb[0];
        out[gw * 3 + 1] = o1 + lb[1];
        out[gw * 3 + 2] = o2 + lb[2];
    }
}

// ---------------- launch ----------------
extern "C" void kernel_launch(void* const* d_in, const int* in_sizes, int n_in,
                              void* d_out, int out_size) {
    const float* x    = (const float*)d_in[0];
    const int*   ei   = (const int*)  d_in[1];
    const float* encW = (const float*)d_in[2];
    const float* encb = (const float*)d_in[3];
    const float* t    = (const float*)d_in[4];
    const float* W1   = (const float*)d_in[5];
    const float* b1   = (const float*)d_in[6];
    const float* mg   = (const float*)d_in[7];
    const float* mb   = (const float*)d_in[8];
    const float* W2   = (const float*)d_in[9];
    const float* b2   = (const float*)d_in[10];
    const float* lng  = (const float*)d_in[11];
    const float* lnb  = (const float*)d_in[12];
    const float* lw   = (const float*)d_in[13];
    const float* lb   = (const float*)d_in[14];
    float* out = (float*)d_out;

    cudaFuncSetAttribute(k_mlp, cudaFuncAttributeMaxDynamicSharedMemorySize, SMEM_MLP_BYTES);

    const int WARP_BLOCKS = (NN * 32 + 255) / 256;
    const int MLP_BLOCKS  = (NN + 63) / 64;

    // CSR build + encoder + weight pre-split (launches 0..2)
    k_enc_hist<<<(NN * HH + 255) / 256, 256>>>(x, encW, encb, ei, W1, W2);
    k_scan<<<NB_SCAN, 1024>>>();
    k_scatter<<<(NE + 255) / 256, 256>>>(ei);

    // layer 0 (launch index 3 = k_agg -> profiled slot); mlp fuses z for layer 1
    k_agg<<<WARP_BLOCKS, 256>>>(t + 0);
    k_mlp<<<MLP_BLOCKS, 256, SMEM_MLP_BYTES>>>(b1, mg, mb, b2,
                                               lng + HH, lnb + HH, 0, 0, 1);

    // layer 1 (mlp fuses z for layer 2), layer 2 (no z)
    k_agg<<<WARP_BLOCKS, 256>>>(t + 1);
    k_mlp<<<MLP_BLOCKS, 256, SMEM_MLP_BYTES>>>(b1 + H2, mg + H2, mb + H2, b2 + HH,
                                               lng + 2 * HH, lnb + 2 * HH, 1, 1, 1);
    k_agg<<<WARP_BLOCKS, 256>>>(t + 2);
    k_mlp<<<MLP_BLOCKS, 256, SMEM_MLP_BYTES>>>(b1 + 2 * H2, mg + 2 * H2, mb + 2 * H2,
                                               b2 + 2 * HH, lng, lnb, 2, 1, 0);

    // final projection (+ scratch re-zero for next replay)
    k_final<<<WARP_BLOCKS, 256>>>(lng, lnb, lw, lb, out);
}

// round 9
// speedup vs baseline: 1.0922x; 1.0922x over previous
#include <cuda_runtime.h>
#include <cuda_bf16.h>
#include <cstdint>

#define NN 100000
#define NE 1200000
#define HH 64
#define H2 128
#define NB_SCAN 98

// ---------------- device scratch (no allocations allowed) ----------------
__device__ float g_z[NN * HH];      // layer input features (fp32)
__device__ float g_h[NN * HH];      // residual stream (fp32)
__device__ unsigned g_uh[NN * 32];  // MLP input, bf16x2 hi words (k-pairs)
__device__ unsigned g_ul[NN * 32];  // MLP input, bf16x2 lo words
__device__ int   g_rowptr[NN + 1];
__device__ int   g_wp[NN];          // zeroed by previous replay's k_final
__device__ int   g_srcs[NE];        // src ids PRE-SCALED by 64
__device__ int   g_sval[128];
__device__ int   g_sincl[128];
__device__ int   g_sflag[128];      // tail-zeroed by k_final
// pre-split weights, [n][kp] rows (k contiguous as bf16):
__device__ unsigned g_w1h[3 * 4096], g_w1l[3 * 4096];
__device__ unsigned g_w2h[3 * 4096], g_w2l[3 * 4096];

// ---------------- helpers ----------------
__device__ __forceinline__ float ex2(float x) {
    float r; asm("ex2.approx.f32 %0, %1;" : "=f"(r) : "f"(x)); return r;
}
__device__ __forceinline__ unsigned pk_bf2(float xe, float xo) {
    unsigned d;
    asm("cvt.rn.bf16x2.f32 %0, %1, %2;" : "=r"(d) : "f"(xo), "f"(xe));
    return d;
}
__device__ __forceinline__ float lo16f(unsigned w) { return __uint_as_float(w << 16); }
__device__ __forceinline__ float hi16f(unsigned w) { return __uint_as_float(w & 0xffff0000u); }
__device__ __forceinline__ void split_pair(float xe, float xo, unsigned& hw, unsigned& lw) {
    hw = pk_bf2(xe, xo);
    lw = pk_bf2(xe - lo16f(hw), xo - hi16f(hw));
}
__device__ __forceinline__ uint32_t smem_u32(const void* p) {
    uint32_t a;
    asm("{ .reg .u64 t; cvta.to.shared.u64 t, %1; cvt.u32.u64 %0, t; }" : "=r"(a) : "l"(p));
    return a;
}
__device__ __forceinline__ void mma16(float* c, unsigned a0, unsigned a1,
                                      unsigned a2, unsigned a3,
                                      unsigned b0, unsigned b1) {
    asm("mma.sync.aligned.m16n8k16.row.col.f32.bf16.bf16.f32 "
        "{%0,%1,%2,%3}, {%4,%5,%6,%7}, {%8,%9}, {%0,%1,%2,%3};"
        : "+f"(c[0]), "+f"(c[1]), "+f"(c[2]), "+f"(c[3])
        : "r"(a0), "r"(a1), "r"(a2), "r"(a3), "r"(b0), "r"(b1));
}
__device__ __forceinline__ void ldsm4(unsigned& r0, unsigned& r1, unsigned& r2,
                                      unsigned& r3, uint32_t addr) {
    asm volatile("ldmatrix.sync.aligned.m8n8.x4.shared.b16 {%0,%1,%2,%3}, [%4];"
                 : "=r"(r0), "=r"(r1), "=r"(r2), "=r"(r3) : "r"(addr));
}

// ------ launch 0: encoder + degree histogram + weight pre-split ------
__global__ void k_enc_hist(const float* __restrict__ x, const float* __restrict__ W,
                           const float* __restrict__ b, const int* __restrict__ ei,
                           const float* __restrict__ W1g, const float* __restrict__ W2g) {
    int idx = blockIdx.x * blockDim.x + threadIdx.x;
    if (idx == 0) g_rowptr[NN] = NE;
    if (idx < NE) atomicAdd(&g_wp[ei[NE + idx]], 1);
    if (idx < NN * HH) {
        int n = idx >> 6, c = idx & 63;
        g_z[idx] = x[n * 3] * W[c] + x[n * 3 + 1] * W[HH + c]
                 + x[n * 3 + 2] * W[2 * HH + c] + b[c];
    }
    if (idx < 3 * 4096) {   // W1^T: idx = l*4096 + n*32 + kp
        int l = idx >> 12, r = idx & 4095, n = r >> 5, kp = r & 31;
        const float* Wl = W1g + l * (HH * H2);
        unsigned hw, lw;
        split_pair(Wl[(2 * kp) * H2 + n], Wl[(2 * kp + 1) * H2 + n], hw, lw);
        g_w1h[idx] = hw; g_w1l[idx] = lw;
    }
    if (idx < 3 * 4096) {   // W2^T: idx = l*4096 + n*64 + kp
        int l = idx >> 12, r = idx & 4095, n = r >> 6, kp = r & 63;
        const float* Wl = W2g + l * (H2 * HH);
        unsigned hw, lw;
        split_pair(Wl[(2 * kp) * HH + n], Wl[(2 * kp + 1) * HH + n], hw, lw);
        g_w2h[idx] = hw; g_w2l[idx] = lw;
    }
}

// ------------- launch 1: single-pass scan (decoupled lookback) -------------
__global__ void k_scan() {
    __shared__ int wsum[32];
    __shared__ int s_excl;
    int t = threadIdx.x, b = blockIdx.x;
    int lane = t & 31, wid = t >> 5;
    int i = b * 1024 + t;
    int x = (i < NN) ? g_wp[i] : 0;

    int v = x;
#pragma unroll
    for (int d = 1; d < 32; d <<= 1) {
        int u = __shfl_up_sync(0xffffffffu, v, d);
        if (lane >= d) v += u;
    }
    if (lane == 31) wsum[wid] = v;
    __syncthreads();
    if (wid == 0) {
        int w = wsum[lane];
#pragma unroll
        for (int d = 1; d < 32; d <<= 1) {
            int u = __shfl_up_sync(0xffffffffu, w, d);
            if (lane >= d) w += u;
        }
        wsum[lane] = w;
    }
    __syncthreads();
    int incl = v + (wid ? wsum[wid - 1] : 0);
    int bsum = wsum[31];

    if (t == 0) {
        if (b == 0) {
            g_sincl[0] = bsum; __threadfence(); g_sflag[0] = 2;
            s_excl = 0;
        } else {
            g_sval[b] = bsum; __threadfence(); g_sflag[b] = 1;
            int excl = 0, j = b - 1;
            while (true) {
                int f;
                do { f = ((volatile int*)g_sflag)[j]; } while (f == 0);
                __threadfence();
                if (f == 2) { excl += ((volatile int*)g_sincl)[j]; break; }
                excl += ((volatile int*)g_sval)[j]; j--;
            }
            g_sincl[b] = excl + bsum; __threadfence(); g_sflag[b] = 2;
            s_excl = excl;
        }
    }
    __syncthreads();
    if (i < NN) {
        int e = s_excl + incl - x;
        g_rowptr[i] = e;
        g_wp[i] = e;
    }
}

// ------------- launch 2: scatter src ids (pre-scaled) into CSR -------------
__global__ void k_scatter(const int* __restrict__ ei) {
    int e = blockIdx.x * blockDim.x + threadIdx.x;
    if (e < NE) {
        int d = ei[NE + e];
        int p = atomicAdd(&g_wp[d], 1);
        g_srcs[p] = ei[e] << 6;   // src * HH
    }
}

// ------- single-pass softmax aggregation (R7 shape: 32 regs, 80% occ) -----
__global__ __launch_bounds__(256, 8) void k_agg(const float* __restrict__ tptr) {
    int gw = (blockIdx.x * blockDim.x + threadIdx.x) >> 5;
    if (gw >= NN) return;
    int lane = threadIdx.x & 31;
    int beg = g_rowptr[gw], end = g_rowptr[gw + 1];
    float tl2 = __ldg(tptr) * 1.44269504f;
    const float* zp = g_z + 2 * lane;

    float z0 = 0.f, z1 = 0.f, s0 = 0.f, s1 = 0.f;
    for (int base = beg; base < end; base += 32) {
        int nn = end - base; if (nn > 32) nn = 32;
        int sid = (base + lane < end) ? __ldg(&g_srcs[base + lane]) : 0;
#pragma unroll 4
        for (int j = 0; j < nn; j++) {
            int s = __shfl_sync(0xffffffffu, sid, j);
            float2 v = *(const float2*)(zp + s);
            float r0 = fmaxf(v.x, 0.f), r1 = fmaxf(v.y, 0.f);
            float w0 = ex2(r0 * tl2);
            float w1 = ex2(r1 * tl2);
            z0 += w0; z1 += w1;
            s0 = fmaf(r0, w0, s0);
            s1 = fmaf(r1, w1, s1);
        }
    }
    float2 zz = *(const float2*)(g_z + gw * HH + 2 * lane);
    float ox = zz.x, oy = zz.y;
    if (end > beg) {
        ox += __fdividef(s0, z0) + 1e-7f;
        oy += __fdividef(s1, z1) + 1e-7f;
    }
    unsigned hw, lw;
    split_pair(ox, oy, hw, lw);
    g_uh[gw * 32 + lane] = hw;
    g_ul[gw * 32 + lane] = lw;
}

// -------- fused MLP: bf16 mma.sync + ldmatrix, 3-term emulated fp32 -------
// also (wz=1) fuses the NEXT layer's z = relu(LN(h)) epilogue.
#define W_PSUM 0
#define W_PSQ  128
#define W_B1   256
#define W_GAM  384
#define W_BET  512
#define W_B2   640
#define W_A    704
#define W_UH   (W_A)
#define W_UL   (W_A + 2304)
#define W_HH   (W_A)
#define W_HL   (W_A + 4352)
#define W_W1H  9408
#define W_W1L  14016
#define W_W2H  18624
#define W_W2L  22976
#define SMEM_MLP_BYTES (27328 * 4)

extern __shared__ unsigned smw[];
__global__ __launch_bounds__(256, 2) void k_mlp(
    const float* __restrict__ b1g, const float* __restrict__ gamg,
    const float* __restrict__ betg, const float* __restrict__ b2g,
    const float* __restrict__ lngN, const float* __restrict__ lnbN,
    int layer, int addm, int wz)
{
    float* smf = (float*)smw;
    int tid = threadIdx.x, w = tid >> 5, lane = tid & 31;
    int g = lane >> 2, t4 = lane & 3;
    int wm = w & 3, wn = w >> 2;
    int n0 = blockIdx.x * 64;
    int lofs = layer * 4096;

    if (tid < 128) {
        smf[W_B1 + tid]  = b1g[tid];
        smf[W_GAM + tid] = gamg[tid];
        smf[W_BET + tid] = betg[tid];
        if (tid < 64) smf[W_B2 + tid] = b2g[tid];
    }
    for (int i = tid * 4; i < 2048; i += 1024) {
        int r = i >> 5, c = i & 31;
        int node = n0 + r;
        uint4 hv = make_uint4(0, 0, 0, 0), lv = hv;
        if (node < NN) {
            hv = *(const uint4*)&g_uh[node * 32 + c];
            lv = *(const uint4*)&g_ul[node * 32 + c];
        }
        *(uint4*)&smw[W_UH + r * 36 + c] = hv;
        *(uint4*)&smw[W_UL + r * 36 + c] = lv;
    }
    for (int i = tid * 4; i < 4096; i += 1024) {
        int r = i >> 5, c = i & 31;
        *(uint4*)&smw[W_W1H + r * 36 + c] = *(const uint4*)&g_w1h[lofs + i];
        *(uint4*)&smw[W_W1L + r * 36 + c] = *(const uint4*)&g_w1l[lofs + i];
    }
    for (int i = tid * 4; i < 4096; i += 1024) {
        int r = i >> 6, c = i & 63;
        *(uint4*)&smw[W_W2H + r * 68 + c] = *(const uint4*)&g_w2h[lofs + i];
        *(uint4*)&smw[W_W2L + r * 68 + c] = *(const uint4*)&g_w2l[lofs + i];
    }
    __syncthreads();

    uint32_t sb = smem_u32(smw);
    int lr = (lane & 7) + ((lane >> 3) & 1) * 8;
    int lhalf = lane >> 4;
    int l8 = lane & 7, lg = lane >> 3;

    // ---- GEMM1 ----
    uint32_t a1H = sb + W_UH * 4 + (16 * wm + lr) * 144 + lhalf * 16;
    uint32_t a1L = a1H + (W_UL - W_UH) * 4;
    uint32_t b1H = sb + W_W1H * 4 + (64 * wn + l8) * 144 + lg * 16;
    uint32_t b1L = b1H + (W_W1L - W_W1H) * 4;

    unsigned aH[4][4], aL[4][4];
#pragma unroll
    for (int ks = 0; ks < 4; ks++) {
        ldsm4(aH[ks][0], aH[ks][1], aH[ks][2], aH[ks][3], a1H + ks * 32);
        ldsm4(aL[ks][0], aL[ks][1], aL[ks][2], aL[ks][3], a1L + ks * 32);
    }
    float c1[8][4];
#pragma unroll
    for (int j = 0; j < 8; j++)
#pragma unroll
        for (int q = 0; q < 4; q++) c1[j][q] = 0.f;

#pragma unroll
    for (int j = 0; j < 8; j++) {
        uint32_t bj = b1H + j * 1152, bjL = b1L + j * 1152;
#pragma unroll
        for (int p = 0; p < 2; p++) {
            unsigned h0, h1, h2, h3, l0, l1, l2, l3;
            ldsm4(h0, h1, h2, h3, bj + p * 64);
            ldsm4(l0, l1, l2, l3, bjL + p * 64);
            int ka = 2 * p, kb = 2 * p + 1;
            mma16(c1[j], aH[ka][0], aH[ka][1], aH[ka][2], aH[ka][3], h0, h1);
            mma16(c1[j], aH[ka][0], aH[ka][1], aH[ka][2], aH[ka][3], l0, l1);
            mma16(c1[j], aL[ka][0], aL[ka][1], aL[ka][2], aL[ka][3], h0, h1);
            mma16(c1[j], aH[kb][0], aH[kb][1], aH[kb][2], aH[kb][3], h2, h3);
            mma16(c1[j], aH[kb][0], aH[kb][1], aH[kb][2], aH[kb][3], l2, l3);
            mma16(c1[j], aL[kb][0], aL[kb][1], aL[kb][2], aL[kb][3], h2, h3);
        }
    }

    // ---- epilogue 1: bias + LN(128) partial sums ----
    int r0 = 16 * wm + g, r1 = r0 + 8;
    float sA = 0.f, sqA = 0.f, sB = 0.f, sqB = 0.f;
#pragma unroll
    for (int j = 0; j < 8; j++) {
        int cb = 64 * wn + 8 * j + 2 * t4;
        float bx = smf[W_B1 + cb], by = smf[W_B1 + cb + 1];
        c1[j][0] += bx; c1[j][1] += by; c1[j][2] += bx; c1[j][3] += by;
        sA += c1[j][0] + c1[j][1];
        sqA = fmaf(c1[j][0], c1[j][0], fmaf(c1[j][1], c1[j][1], sqA));
        sB += c1[j][2] + c1[j][3];
        sqB = fmaf(c1[j][2], c1[j][2], fmaf(c1[j][3], c1[j][3], sqB));
    }
    sA += __shfl_xor_sync(0xffffffffu, sA, 1);  sA += __shfl_xor_sync(0xffffffffu, sA, 2);
    sqA += __shfl_xor_sync(0xffffffffu, sqA, 1); sqA += __shfl_xor_sync(0xffffffffu, sqA, 2);
    sB += __shfl_xor_sync(0xffffffffu, sB, 1);  sB += __shfl_xor_sync(0xffffffffu, sB, 2);
    sqB += __shfl_xor_sync(0xffffffffu, sqB, 1); sqB += __shfl_xor_sync(0xffffffffu, sqB, 2);
    if (t4 == 0) {
        smf[W_PSUM + wn * 64 + r0] = sA;  smf[W_PSQ + wn * 64 + r0] = sqA;
        smf[W_PSUM + wn * 64 + r1] = sB;  smf[W_PSQ + wn * 64 + r1] = sqB;
    }
    __syncthreads();

    float s0 = smf[W_PSUM + r0] + smf[W_PSUM + 64 + r0];
    float q0 = smf[W_PSQ + r0]  + smf[W_PSQ + 64 + r0];
    float s1 = smf[W_PSUM + r1] + smf[W_PSUM + 64 + r1];
    float q1 = smf[W_PSQ + r1]  + smf[W_PSQ + 64 + r1];
    float mu0 = s0 * (1.f / 128.f), mu1 = s1 * (1.f / 128.f);
    float rs0 = rsqrtf(q0 * (1.f / 128.f) - mu0 * mu0 + 1e-5f);
    float rs1 = rsqrtf(q1 * (1.f / 128.f) - mu1 * mu1 + 1e-5f);

#pragma unroll
    for (int j = 0; j < 8; j++) {
        int cb = 64 * wn + 8 * j + 2 * t4;
        float gx = smf[W_GAM + cb], gy = smf[W_GAM + cb + 1];
        float ex = smf[W_BET + cb], ey = smf[W_BET + cb + 1];
        float h0 = fmaxf((c1[j][0] - mu0) * rs0 * gx + ex, 0.f);
        float h1 = fmaxf((c1[j][1] - mu0) * rs0 * gy + ey, 0.f);
        float h2 = fmaxf((c1[j][2] - mu1) * rs1 * gx + ex, 0.f);
        float h3 = fmaxf((c1[j][3] - mu1) * rs1 * gy + ey, 0.f);
        int kp = cb >> 1;
        unsigned hw, lw;
        split_pair(h0, h1, hw, lw);
        smw[W_HH + r0 * 68 + kp] = hw; smw[W_HL + r0 * 68 + kp] = lw;
        split_pair(h2, h3, hw, lw);
        smw[W_HH + r1 * 68 + kp] = hw; smw[W_HL + r1 * 68 + kp] = lw;
    }
    __syncthreads();

    // ---- GEMM2 ----
    uint32_t a2H = sb + W_HH * 4 + (16 * wm + lr) * 272 + lhalf * 16;
    uint32_t a2L = a2H + (W_HL - W_HH) * 4;
    uint32_t b2H = sb + W_W2H * 4 + (32 * wn + l8) * 272 + lg * 16;
    uint32_t b2L = b2H + (W_W2L - W_W2H) * 4;

    float c2[4][4];
#pragma unroll
    for (int j = 0; j < 4; j++)
#pragma unroll
        for (int q = 0; q < 4; q++) c2[j][q] = 0.f;

#pragma unroll
    for (int p = 0; p < 4; p++) {
        unsigned xh[8], xl[8];
        ldsm4(xh[0], xh[1], xh[2], xh[3], a2H + p * 64);
        ldsm4(xh[4], xh[5], xh[6], xh[7], a2H + p * 64 + 32);
        ldsm4(xl[0], xl[1], xl[2], xl[3], a2L + p * 64);
        ldsm4(xl[4], xl[5], xl[6], xl[7], a2L + p * 64 + 32);
#pragma unroll
        for (int j = 0; j < 4; j++) {
            unsigned h0, h1, h2, h3, l0, l1, l2, l3;
            ldsm4(h0, h1, h2, h3, b2H + j * 2176 + p * 64);
            ldsm4(l0, l1, l2, l3, b2L + j * 2176 + p * 64);
            mma16(c2[j], xh[0], xh[1], xh[2], xh[3], h0, h1);
            mma16(c2[j], xh[0], xh[1], xh[2], xh[3], l0, l1);
            mma16(c2[j], xl[0], xl[1], xl[2], xl[3], h0, h1);
            mma16(c2[j], xh[4], xh[5], xh[6], xh[7], h2, h3);
            mma16(c2[j], xh[4], xh[5], xh[6], xh[7], l2, l3);
            mma16(c2[j], xl[4], xl[5], xl[6], xl[7], h2, h3);
        }
    }

    // ---- epilogue 2: bias (+residual) -> g_h ; keep final h in c2 ----
    int node0 = n0 + r0, node1 = n0 + r1;
    float ps0 = 0.f, pq0 = 0.f, ps1 = 0.f, pq1 = 0.f;
#pragma unroll
    for (int j = 0; j < 4; j++) {
        int cb = 32 * wn + 8 * j + 2 * t4;
        float bx = smf[W_B2 + cb], by = smf[W_B2 + cb + 1];
        float h00 = c2[j][0] + bx, h01 = c2[j][1] + by;
        float h10 = c2[j][2] + bx, h11 = c2[j][3] + by;
        if (node0 < NN) {
            float* dst = g_h + node0 * HH + cb;
            if (addm) { float2 pv = *(const float2*)dst; h00 += pv.x; h01 += pv.y; }
            *(float2*)dst = make_float2(h00, h01);
        }
        if (node1 < NN) {
            float* dst = g_h + node1 * HH + cb;
            if (addm) { float2 pv = *(const float2*)dst; h10 += pv.x; h11 += pv.y; }
            *(float2*)dst = make_float2(h10, h11);
        }
        c2[j][0] = h00; c2[j][1] = h01; c2[j][2] = h10; c2[j][3] = h11;
        ps0 += h00 + h01; pq0 = fmaf(h00, h00, fmaf(h01, h01, pq0));
        ps1 += h10 + h11; pq1 = fmaf(h10, h10, fmaf(h11, h11, pq1));
    }

    // ---- fused z = relu(LN_{next}(h)) (wz layers only) ----
    if (wz) {
        ps0 += __shfl_xor_sync(0xffffffffu, ps0, 1); ps0 += __shfl_xor_sync(0xffffffffu, ps0, 2);
        pq0 += __shfl_xor_sync(0xffffffffu, pq0, 1); pq0 += __shfl_xor_sync(0xffffffffu, pq0, 2);
        ps1 += __shfl_xor_sync(0xffffffffu, ps1, 1); ps1 += __shfl_xor_sync(0xffffffffu, ps1, 2);
        pq1 += __shfl_xor_sync(0xffffffffu, pq1, 1); pq1 += __shfl_xor_sync(0xffffffffu, pq1, 2);
        if (t4 == 0) {
            smf[W_PSUM + wn * 64 + r0] = ps0;  smf[W_PSQ + wn * 64 + r0] = pq0;
            smf[W_PSUM + wn * 64 + r1] = ps1;  smf[W_PSQ + wn * 64 + r1] = pq1;
        }
        __syncthreads();
        float S0 = smf[W_PSUM + r0] + smf[W_PSUM + 64 + r0];
        float Q0 = smf[W_PSQ + r0]  + smf[W_PSQ + 64 + r0];
        float S1 = smf[W_PSUM + r1] + smf[W_PSUM + 64 + r1];
        float Q1 = smf[W_PSQ + r1]  + smf[W_PSQ + 64 + r1];
        float m0 = S0 * (1.f / 64.f), m1 = S1 * (1.f / 64.f);
        float v0 = rsqrtf(Q0 * (1.f / 64.f) - m0 * m0 + 1e-5f);
        float v1 = rsqrtf(Q1 * (1.f / 64.f) - m1 * m1 + 1e-5f);
#pragma unroll
        for (int j = 0; j < 4; j++) {
            int cb = 32 * wn + 8 * j + 2 * t4;
            float gx = __ldg(&lngN[cb]), gy = __ldg(&lngN[cb + 1]);
            float ex = __ldg(&lnbN[cb]), ey = __ldg(&lnbN[cb + 1]);
            if (node0 < NN) {
                float z0 = fmaxf((c2[j][0] - m0) * v0 * gx + ex, 0.f);
                float z1 = fmaxf((c2[j][1] - m0) * v0 * gy + ey, 0.f);
                *(float2*)(g_z + node0 * HH + cb) = make_float2(z0, z1);
            }
            if (node1 < NN) {
                float z0 = fmaxf((c2[j][2] - m1) * v1 * gx + ex, 0.f);
                float z1 = fmaxf((c2[j][3] - m1) * v1 * gy + ey, 0.f);
                *(float2*)(g_z + node1 * HH + cb) = make_float2(z0, z1);
            }
        }
    }
}

// -------- final: relu(LN(h)) @ lin_W + lin_b ; also re-zero scratch --------
__global__ void k_final(const float* __restrict__ g, const float* __restrict__ b,
                        const float* __restrict__ lw, const float* __restrict__ lb,
                        float* __restrict__ out) {
    int gw = (blockIdx.x * blockDim.x + threadIdx.x) >> 5;
    if (gw >= NN) return;
    int lane = threadIdx.x & 31;
    if (lane == 1) g_wp[gw] = 0;
    if (gw < 128 && lane == 2) g_sflag[gw] = 0;

    float2 v = *(const float2*)(g_h + gw * HH + 2 * lane);
    float s = v.x + v.y, sq = v.x * v.x + v.y * v.y;
    for (int o = 16; o; o >>= 1) {
        s  += __shfl_xor_sync(0xffffffffu, s, o);
        sq += __shfl_xor_sync(0xffffffffu, sq, o);
    }
    float mu = s * 0.015625f;
    float var = sq * 0.015625f - mu * mu;
    float rs = rsqrtf(var + 1e-5f);
    float a0 = fmaxf((v.x - mu) * rs * g[2 * lane]     + b[2 * lane],     0.f);
    float a1 = fmaxf((v.y - mu) * rs * g[2 * lane + 1] + b[2 * lane + 1], 0.f);
    float o0 = a0 * lw[(2 * lane) * 3 + 0] + a1 * lw[(2 * lane + 1) * 3 + 0];
    float o1 = a0 * lw[(2 * lane) * 3 + 1] + a1 * lw[(2 * lane + 1) * 3 + 1];
    float o2 = a0 * lw[(2 * lane) * 3 + 2] + a1 * lw[(2 * lane + 1) * 3 + 2];
    for (int ww = 16; ww; ww >>= 1) {
        o0 += __shfl_xor_sync(0xffffffffu, o0, ww);
        o1 += __shfl_xor_sync(0xffffffffu, o1, ww);
        o2 += __shfl_xor_sync(0xffffffffu, o2, ww);
    }
    if (lane == 0) {
        out[gw * 3 + 0] = o0 + lb[0];
        out[gw * 3 + 1] = o1 + lb[1];
        out[gw * 3 + 2] = o2 + lb[2];
    }
}

// ---------------- launch ----------------
extern "C" void kernel_launch(void* const* d_in, const int* in_sizes, int n_in,
                              void* d_out, int out_size) {
    const float* x    = (const float*)d_in[0];
    const int*   ei   = (const int*)  d_in[1];
    const float* encW = (const float*)d_in[2];
    const float* encb = (const float*)d_in[3];
    const float* t    = (const float*)d_in[4];
    const float* W1   = (const float*)d_in[5];
    const float* b1   = (const float*)d_in[6];
    const float* mg   = (const float*)d_in[7];
    const float* mb   = (const float*)d_in[8];
    const float* W2   = (const float*)d_in[9];
    const float* b2   = (const float*)d_in[10];
    const float* lng  = (const float*)d_in[11];
    const float* lnb  = (const float*)d_in[12];
    const float* lw   = (const float*)d_in[13];
    const float* lb   = (const float*)d_in[14];
    float* out = (float*)d_out;

    cudaFuncSetAttribute(k_mlp, cudaFuncAttributeMaxDynamicSharedMemorySize, SMEM_MLP_BYTES);

    const int WARP_BLOCKS = (NN * 32 + 255) / 256;
    const int MLP_BLOCKS  = (NN + 63) / 64;

    // CSR build + encoder + weight pre-split (launches 0..2)
    k_enc_hist<<<(NN * HH + 255) / 256, 256>>>(x, encW, encb, ei, W1, W2);
    k_scan<<<NB_SCAN, 1024>>>();
    k_scatter<<<(NE + 255) / 256, 256>>>(ei);

    // layer 0 (launch index 3 = k_agg -> profiled slot); mlp fuses z for layer 1
    k_agg<<<WARP_BLOCKS, 256>>>(t + 0);
    k_mlp<<<MLP_BLOCKS, 256, SMEM_MLP_BYTES>>>(b1, mg, mb, b2,
                                               lng + HH, lnb + HH, 0, 0, 1);

    // layer 1 (mlp fuses z for layer 2), layer 2 (no z)
    k_agg<<<WARP_BLOCKS, 256>>>(t + 1);
    k_mlp<<<MLP_BLOCKS, 256, SMEM_MLP_BYTES>>>(b1 + H2, mg + H2, mb + H2, b2 + HH,
                                               lng + 2 * HH, lnb + 2 * HH, 1, 1, 1);
    k_agg<<<WARP_BLOCKS, 256>>>(t + 2);
    k_mlp<<<MLP_BLOCKS, 256, SMEM_MLP_BYTES>>>(b1 + 2 * H2, mg + 2 * H2, mb + 2 * H2,
                                               b2 + 2 * HH, lng, lnb, 2, 1, 0);

    // final projection (+ scratch re-zero for next replay)
    k_final<<<WARP_BLOCKS, 256>>>(lng, lnb, lw, lb, out);
}